// round 2
// baseline (speedup 1.0000x reference)
#include <cuda_runtime.h>
#include <math.h>

#define BB 8
#define LL 8192
#define DD 256
#define WW 64
#define NW 128
#define RW 512  /* B*W reduction rows per window */

// Scratch (allocation-free rule: static __device__ arrays)
__device__ float g_A[(size_t)NW * DD * DD];    // A_n = a*I - Skk_n   (32 MB)
__device__ float g_Svk[(size_t)NW * DD * DD];  // Svk_n               (32 MB)
__device__ float g_Ms[(size_t)NW * DD * DD];   // M snapshots         (32 MB)

// ---------------------------------------------------------------------------
// Kernel 1: per-window sums.
//   Skk_n[i,j] = sum_{r=0..511} g_r * K_r[i] * K_r[j]
//   Svk_n[i,j] = sum_{r=0..511} g_r * V_r[i] * K_r[j]
// grid (4, 4, NW*2): z even -> A (=aI-Skk), z odd -> Svk. block (16,16).
// Each CTA: 64x64 tile, reduction over 512 rows in steps of 16.
// ---------------------------------------------------------------------------
__global__ __launch_bounds__(256) void k_sums(const float* __restrict__ keys,
                                              const float* __restrict__ values,
                                              const float* __restrict__ gammas,
                                              const float* __restrict__ alpha) {
    const int n    = blockIdx.z >> 1;
    const bool isA = (blockIdx.z & 1) == 0;
    const int jBase = blockIdx.x * 64;
    const int iBase = blockIdx.y * 64;
    const float* left = isA ? keys : values;

    __shared__ float Ls[16][64];
    __shared__ float Rs[16][64];

    const int tx = threadIdx.x, ty = threadIdx.y;
    const int tid = ty * 16 + tx;
    const int rr = tid >> 4;          // 0..15 (reduction row within tile)
    const int cc = (tid & 15) * 4;    // 0..60 (column, float4)

    float acc[4][4];
#pragma unroll
    for (int a = 0; a < 4; a++)
#pragma unroll
        for (int b = 0; b < 4; b++) acc[a][b] = 0.f;

    for (int r0 = 0; r0 < RW; r0 += 16) {
        const int r = r0 + rr;
        const int b = r >> 6;
        const int w = r & 63;
        const int l = n * WW + w;
        const size_t rowoff = ((size_t)b * LL + l) * DD;
        const float g = gammas[b * LL + l];
        float4 lv = *(const float4*)(left + rowoff + iBase + cc);
        float4 rv = *(const float4*)(keys + rowoff + jBase + cc);

        __syncthreads();  // previous tile fully consumed
        lv.x *= g; lv.y *= g; lv.z *= g; lv.w *= g;
        *(float4*)&Ls[rr][cc] = lv;
        *(float4*)&Rs[rr][cc] = rv;
        __syncthreads();

#pragma unroll
        for (int kk = 0; kk < 16; kk++) {
            float la[4], lb[4];
            *(float4*)la = *(const float4*)&Ls[kk][ty * 4];
            *(float4*)lb = *(const float4*)&Rs[kk][tx * 4];
#pragma unroll
            for (int a = 0; a < 4; a++)
#pragma unroll
                for (int b = 0; b < 4; b++) acc[a][b] = fmaf(la[a], lb[b], acc[a][b]);
        }
    }

    const float aSig = 1.f / (1.f + expf(-alpha[0]));
    float* dst = isA ? g_A : g_Svk;
    const size_t base = (size_t)n * DD * DD;
#pragma unroll
    for (int a = 0; a < 4; a++) {
        const int i = iBase + ty * 4 + a;
#pragma unroll
        for (int b = 0; b < 4; b++) {
            const int j = jBase + tx * 4 + b;
            float v = acc[a][b];
            if (isA) v = ((i == j) ? aSig : 0.f) - v;
            dst[base + (size_t)i * DD + j] = v;
        }
    }
}

// ---------------------------------------------------------------------------
// Kernel 2: sequential scan, row-parallel.
//   M_n[r, j] = sum_d M_{n-1}[r, d] * A_n[d, j] + Svk_n[r, j]
// grid 64 CTAs x 4 rows, block 256 (thread = column j). No inter-CTA deps.
// ---------------------------------------------------------------------------
__global__ __launch_bounds__(256) void k_scan() {
    __shared__ float Msm[4][DD];
    const int j = threadIdx.x;
    const int r0 = blockIdx.x * 4;

    Msm[0][j] = 0.f; Msm[1][j] = 0.f; Msm[2][j] = 0.f; Msm[3][j] = 0.f;
    __syncthreads();

    for (int n = 0; n < NW; n++) {
        const float* __restrict__ A = g_A + (size_t)n * DD * DD;
        const float* __restrict__ S = g_Svk + (size_t)n * DD * DD + (size_t)r0 * DD;

        float t0 = S[j];
        float t1 = S[DD + j];
        float t2 = S[2 * DD + j];
        float t3 = S[3 * DD + j];

#pragma unroll 8
        for (int d = 0; d < DD; d += 4) {
            const float av0 = A[(size_t)(d + 0) * DD + j];
            const float av1 = A[(size_t)(d + 1) * DD + j];
            const float av2 = A[(size_t)(d + 2) * DD + j];
            const float av3 = A[(size_t)(d + 3) * DD + j];
            const float4 m0 = *(const float4*)&Msm[0][d];
            const float4 m1 = *(const float4*)&Msm[1][d];
            const float4 m2 = *(const float4*)&Msm[2][d];
            const float4 m3 = *(const float4*)&Msm[3][d];
            t0 = fmaf(m0.x, av0, t0); t0 = fmaf(m0.y, av1, t0);
            t0 = fmaf(m0.z, av2, t0); t0 = fmaf(m0.w, av3, t0);
            t1 = fmaf(m1.x, av0, t1); t1 = fmaf(m1.y, av1, t1);
            t1 = fmaf(m1.z, av2, t1); t1 = fmaf(m1.w, av3, t1);
            t2 = fmaf(m2.x, av0, t2); t2 = fmaf(m2.y, av1, t2);
            t2 = fmaf(m2.z, av2, t2); t2 = fmaf(m2.w, av3, t2);
            t3 = fmaf(m3.x, av0, t3); t3 = fmaf(m3.y, av1, t3);
            t3 = fmaf(m3.z, av2, t3); t3 = fmaf(m3.w, av3, t3);
        }

        __syncthreads();  // all reads of Msm complete
        Msm[0][j] = t0; Msm[1][j] = t1; Msm[2][j] = t2; Msm[3][j] = t3;
        float* __restrict__ Mo = g_Ms + (size_t)n * DD * DD + (size_t)r0 * DD;
        Mo[j] = t0; Mo[DD + j] = t1; Mo[2 * DD + j] = t2; Mo[3 * DD + j] = t3;
        __syncthreads();  // new Msm visible before next iteration reads
    }
}

// ---------------------------------------------------------------------------
// Kernel 3: retrieval.  out[b, n*W+w, o] = sum_d Q[b, n*W+w, d] * Ms_n[o, d]
// NT-gemm per window: CTA = (o-tile 64, batch, window). block (16,16).
// Both operands reduced along contiguous d -> transpose into smem.
// ---------------------------------------------------------------------------
__global__ __launch_bounds__(256) void k_out(const float* __restrict__ queries,
                                             float* __restrict__ out) {
    const int n = blockIdx.z;
    const int b = blockIdx.y;             // batch = query-row tile (64 rows = one batch's window)
    const int oBase = blockIdx.x * 64;

    __shared__ float Qs[16][68];   // [d-sub][query row]
    __shared__ float Mss[16][68];  // [d-sub][o]

    const int tx = threadIdx.x, ty = threadIdx.y;
    const int tid = ty * 16 + tx;
    const int lr = tid >> 2;            // 0..63
    const int dd = (tid & 3) * 4;       // 0,4,8,12

    const float* __restrict__ Qbase = queries + ((size_t)b * LL + (size_t)n * WW) * DD;
    const float* __restrict__ Mbase = g_Ms + (size_t)n * DD * DD;

    float acc[4][4];
#pragma unroll
    for (int a = 0; a < 4; a++)
#pragma unroll
        for (int c = 0; c < 4; c++) acc[a][c] = 0.f;

    for (int d0 = 0; d0 < DD; d0 += 16) {
        const float4 qv = *(const float4*)(Qbase + (size_t)lr * DD + d0 + dd);
        const float4 mv = *(const float4*)(Mbase + (size_t)(oBase + lr) * DD + d0 + dd);
        __syncthreads();
        Qs[dd + 0][lr] = qv.x; Qs[dd + 1][lr] = qv.y;
        Qs[dd + 2][lr] = qv.z; Qs[dd + 3][lr] = qv.w;
        Mss[dd + 0][lr] = mv.x; Mss[dd + 1][lr] = mv.y;
        Mss[dd + 2][lr] = mv.z; Mss[dd + 3][lr] = mv.w;
        __syncthreads();

#pragma unroll
        for (int kk = 0; kk < 16; kk++) {
            float la[4], lb[4];
#pragma unroll
            for (int a = 0; a < 4; a++) la[a] = Qs[kk][ty * 4 + a];
#pragma unroll
            for (int c = 0; c < 4; c++) lb[c] = Mss[kk][tx * 4 + c];
#pragma unroll
            for (int a = 0; a < 4; a++)
#pragma unroll
                for (int c = 0; c < 4; c++) acc[a][c] = fmaf(la[a], lb[c], acc[a][c]);
        }
    }

#pragma unroll
    for (int a = 0; a < 4; a++) {
        const int w = ty * 4 + a;
        const size_t orow = ((size_t)b * LL + (size_t)n * WW + w) * DD;
#pragma unroll
        for (int c = 0; c < 4; c++) {
            out[orow + oBase + tx * 4 + c] = acc[a][c];
        }
    }
}

// ---------------------------------------------------------------------------
extern "C" void kernel_launch(void* const* d_in, const int* in_sizes, int n_in,
                              void* d_out, int out_size) {
    const float* keys    = (const float*)d_in[0];
    const float* values  = (const float*)d_in[1];
    const float* queries = (const float*)d_in[2];
    const float* gammas  = (const float*)d_in[3];
    const float* alpha   = (const float*)d_in[4];
    float* out = (float*)d_out;

    (void)in_sizes; (void)n_in; (void)out_size;

    dim3 blk(16, 16);
    k_sums<<<dim3(4, 4, NW * 2), blk>>>(keys, values, gammas, alpha);
    k_scan<<<64, 256>>>();
    k_out<<<dim3(4, BB, NW), blk>>>(queries, out);
}

// round 3
// speedup vs baseline: 2.2471x; 2.2471x over previous
#include <cuda_runtime.h>
#include <math.h>

#define BB 8
#define LL 8192
#define DD 256
#define WW 64
#define NW 128
#define RW 512   /* B*W reduction rows per window */
#define LB 132   /* padded smem row stride (floats): 132 mod 32 = 4 -> 2-way max */

// Scratch (allocation-free rule: static __device__ arrays)
__device__ float g_A[(size_t)NW * DD * DD];    // A_n = a*I - Skk_n   (32 MB)
__device__ float g_Svk[(size_t)NW * DD * DD];  // Svk_n               (32 MB)
__device__ float g_Ms[(size_t)NW * DD * DD];   // M snapshots         (32 MB)

// ---------------------------------------------------------------------------
// Kernel 1: per-window sums.
//   Skk_n[i,j] = sum_r g_r K_r[i] K_r[j];  Svk_n[i,j] = sum_r g_r V_r[i] K_r[j]
// grid (2, 2, NW*2): z even -> A (= aI - Skk), z odd -> Svk. block (16,16).
// 128x128 tile, 8x8 per-thread register tile, K-chunk 16, reg prefetch.
// ---------------------------------------------------------------------------
__global__ __launch_bounds__(256, 2) void k_sums(const float* __restrict__ keysp,
                                                 const float* __restrict__ values,
                                                 const float* __restrict__ gammas,
                                                 const float* __restrict__ alpha) {
    const int n    = blockIdx.z >> 1;
    const bool isA = (blockIdx.z & 1) == 0;
    const int jBase = blockIdx.x * 128;
    const int iBase = blockIdx.y * 128;
    const float* __restrict__ left = isA ? keysp : values;

    __shared__ float Ls[16 * LB];
    __shared__ float Rs[16 * LB];

    const int tx = threadIdx.x, ty = threadIdx.y;
    const int tid = ty * 16 + tx;
    // loader slots s = tid, tid+256: row = s>>5 (0..15), col4 = s&31
    const int row0 = tid >> 5;          // 0..7
    const int row1 = row0 + 8;          // 8..15
    const int c4   = (tid & 31) * 4;    // 0..124

    float acc[8][8];
#pragma unroll
    for (int a = 0; a < 8; a++)
#pragma unroll
        for (int b = 0; b < 8; b++) acc[a][b] = 0.f;

    float4 lA0, lA1, rA0, rA1;
    float g0v, g1v;

#define LOADC(R0) do {                                                        \
        const int gr0 = (R0) + row0, gr1 = (R0) + row1;                       \
        const size_t o0 = ((size_t)(gr0 >> 6) * LL + n * WW + (gr0 & 63)) * DD; \
        const size_t o1 = ((size_t)(gr1 >> 6) * LL + n * WW + (gr1 & 63)) * DD; \
        g0v = gammas[(gr0 >> 6) * LL + n * WW + (gr0 & 63)];                  \
        g1v = gammas[(gr1 >> 6) * LL + n * WW + (gr1 & 63)];                  \
        lA0 = *(const float4*)(left  + o0 + iBase + c4);                      \
        lA1 = *(const float4*)(left  + o1 + iBase + c4);                      \
        rA0 = *(const float4*)(keysp + o0 + jBase + c4);                      \
        rA1 = *(const float4*)(keysp + o1 + jBase + c4);                      \
    } while (0)

    LOADC(0);

    for (int c = 0; c < 32; c++) {
        __syncthreads();
        float4 t;
        t = lA0; t.x *= g0v; t.y *= g0v; t.z *= g0v; t.w *= g0v;
        *(float4*)&Ls[row0 * LB + c4] = t;
        t = lA1; t.x *= g1v; t.y *= g1v; t.z *= g1v; t.w *= g1v;
        *(float4*)&Ls[row1 * LB + c4] = t;
        *(float4*)&Rs[row0 * LB + c4] = rA0;
        *(float4*)&Rs[row1 * LB + c4] = rA1;
        __syncthreads();
        if (c < 31) LOADC((c + 1) * 16);

#pragma unroll
        for (int kk = 0; kk < 16; kk++) {
            float la[8], lb[8];
            *(float4*)&la[0] = *(const float4*)&Ls[kk * LB + ty * 8];
            *(float4*)&la[4] = *(const float4*)&Ls[kk * LB + ty * 8 + 4];
            *(float4*)&lb[0] = *(const float4*)&Rs[kk * LB + tx * 8];
            *(float4*)&lb[4] = *(const float4*)&Rs[kk * LB + tx * 8 + 4];
#pragma unroll
            for (int a = 0; a < 8; a++)
#pragma unroll
                for (int b = 0; b < 8; b++) acc[a][b] = fmaf(la[a], lb[b], acc[a][b]);
        }
    }
#undef LOADC

    const float aSig = 1.f / (1.f + expf(-alpha[0]));
    float* dst = isA ? g_A : g_Svk;
    const size_t base = (size_t)n * DD * DD;
#pragma unroll
    for (int a = 0; a < 8; a++) {
        const int i = iBase + ty * 8 + a;
#pragma unroll
        for (int b = 0; b < 8; b++) {
            const int j = jBase + tx * 8 + b;
            float v = acc[a][b];
            if (isA) v = ((i == j) ? aSig : 0.f) - v;
            acc[a][b] = v;
        }
        *(float4*)(dst + base + (size_t)i * DD + jBase + tx * 8)     = *(float4*)&acc[a][0];
        *(float4*)(dst + base + (size_t)i * DD + jBase + tx * 8 + 4) = *(float4*)&acc[a][4];
    }
}

// ---------------------------------------------------------------------------
// Kernel 2: sequential scan, row-parallel.
//   M_n[r, j] = sum_d M_{n-1}[r, d] * A_n[d, j] + Svk_n[r, j]
// grid 64 CTAs x 4 rows, block 512: thread = (j = t&255, h = t>>8).
// Each half sums 128 d's (MLP-16 batched LDG), partials combined in smem.
// ---------------------------------------------------------------------------
__global__ __launch_bounds__(512) void k_scan() {
    __shared__ float Msm[4][DD];
    __shared__ float part[2][4][DD];
    const int j = threadIdx.x & 255;
    const int h = threadIdx.x >> 8;
    const int r0 = blockIdx.x * 4;
    const int dBase = h * 128;

    if (h == 0) { Msm[0][j] = 0.f; Msm[1][j] = 0.f; Msm[2][j] = 0.f; Msm[3][j] = 0.f; }
    __syncthreads();

    for (int n = 0; n < NW; n++) {
        const float* __restrict__ A = g_A + (size_t)n * DD * DD;
        const float* __restrict__ S = g_Svk + (size_t)n * DD * DD + (size_t)r0 * DD;

        float t0, t1, t2, t3;
        if (h == 0) { t0 = S[j]; t1 = S[DD + j]; t2 = S[2 * DD + j]; t3 = S[3 * DD + j]; }
        else        { t0 = 0.f; t1 = 0.f; t2 = 0.f; t3 = 0.f; }

#pragma unroll 2
        for (int d0 = 0; d0 < 128; d0 += 16) {
            float av[16];
#pragma unroll
            for (int k = 0; k < 16; k++)
                av[k] = A[(size_t)(dBase + d0 + k) * DD + j];
#pragma unroll
            for (int k = 0; k < 16; k += 4) {
                const float4 m0 = *(const float4*)&Msm[0][dBase + d0 + k];
                const float4 m1 = *(const float4*)&Msm[1][dBase + d0 + k];
                const float4 m2 = *(const float4*)&Msm[2][dBase + d0 + k];
                const float4 m3 = *(const float4*)&Msm[3][dBase + d0 + k];
                t0 = fmaf(m0.x, av[k], t0); t0 = fmaf(m0.y, av[k + 1], t0);
                t0 = fmaf(m0.z, av[k + 2], t0); t0 = fmaf(m0.w, av[k + 3], t0);
                t1 = fmaf(m1.x, av[k], t1); t1 = fmaf(m1.y, av[k + 1], t1);
                t1 = fmaf(m1.z, av[k + 2], t1); t1 = fmaf(m1.w, av[k + 3], t1);
                t2 = fmaf(m2.x, av[k], t2); t2 = fmaf(m2.y, av[k + 1], t2);
                t2 = fmaf(m2.z, av[k + 2], t2); t2 = fmaf(m2.w, av[k + 3], t2);
                t3 = fmaf(m3.x, av[k], t3); t3 = fmaf(m3.y, av[k + 1], t3);
                t3 = fmaf(m3.z, av[k + 2], t3); t3 = fmaf(m3.w, av[k + 3], t3);
            }
        }

        part[h][0][j] = t0; part[h][1][j] = t1; part[h][2][j] = t2; part[h][3][j] = t3;
        __syncthreads();

        const float u0 = part[0][0][j] + part[1][0][j];
        const float u1 = part[0][1][j] + part[1][1][j];
        const float u2 = part[0][2][j] + part[1][2][j];
        const float u3 = part[0][3][j] + part[1][3][j];
        if (h == 0) {
            Msm[0][j] = u0; Msm[1][j] = u1; Msm[2][j] = u2; Msm[3][j] = u3;
        } else {
            float* __restrict__ Mo = g_Ms + (size_t)n * DD * DD + (size_t)r0 * DD;
            Mo[j] = u0; Mo[DD + j] = u1; Mo[2 * DD + j] = u2; Mo[3 * DD + j] = u3;
        }
        __syncthreads();
    }
}

// ---------------------------------------------------------------------------
// Kernel 3: retrieval.  out[b, n*W+w, o] = sum_d Q[b, n*W+w, d] * Ms_n[o, d]
// grid (2, 4, NW): x = o-tile(128), y = qrow-tile(128 of 512), z = window.
// Same 8x8 register-tile engine; operands transposed into padded smem.
// ---------------------------------------------------------------------------
__global__ __launch_bounds__(256, 2) void k_out(const float* __restrict__ queries,
                                                float* __restrict__ out) {
    const int n = blockIdx.z;
    const int oBase = blockIdx.x * 128;
    const int uBase = blockIdx.y * 128;

    __shared__ float Qs[16 * LB];   // [d][u]
    __shared__ float Mss[16 * LB];  // [d][o]

    const int tx = threadIdx.x, ty = threadIdx.y;
    const int tid = ty * 16 + tx;
    // loader slots s = tid, tid+256: u_local = s>>2 (0..127), dq = (s&3)*4
    const int ul0 = tid >> 2;         // 0..63
    const int ul1 = ul0 + 64;         // 64..127
    const int dq  = (tid & 3) * 4;    // 0,4,8,12

    const float* __restrict__ Mbase = g_Ms + (size_t)n * DD * DD;

    // global q rows for the two loader slots
    const int ug0 = uBase + ul0, ug1 = uBase + ul1;
    const size_t qoff0 = ((size_t)(ug0 >> 6) * LL + n * WW + (ug0 & 63)) * DD;
    const size_t qoff1 = ((size_t)(ug1 >> 6) * LL + n * WW + (ug1 & 63)) * DD;

    float acc[8][8];
#pragma unroll
    for (int a = 0; a < 8; a++)
#pragma unroll
        for (int c = 0; c < 8; c++) acc[a][c] = 0.f;

    float4 q0, q1, m0, m1;
#define LOADD(D0) do {                                                        \
        q0 = *(const float4*)(queries + qoff0 + (D0) + dq);                   \
        q1 = *(const float4*)(queries + qoff1 + (D0) + dq);                   \
        m0 = *(const float4*)(Mbase + (size_t)(oBase + ul0) * DD + (D0) + dq);\
        m1 = *(const float4*)(Mbase + (size_t)(oBase + ul1) * DD + (D0) + dq);\
    } while (0)

    LOADD(0);

    for (int c = 0; c < 16; c++) {
        __syncthreads();
        Qs[(dq + 0) * LB + ul0] = q0.x; Qs[(dq + 1) * LB + ul0] = q0.y;
        Qs[(dq + 2) * LB + ul0] = q0.z; Qs[(dq + 3) * LB + ul0] = q0.w;
        Qs[(dq + 0) * LB + ul1] = q1.x; Qs[(dq + 1) * LB + ul1] = q1.y;
        Qs[(dq + 2) * LB + ul1] = q1.z; Qs[(dq + 3) * LB + ul1] = q1.w;
        Mss[(dq + 0) * LB + ul0] = m0.x; Mss[(dq + 1) * LB + ul0] = m0.y;
        Mss[(dq + 2) * LB + ul0] = m0.z; Mss[(dq + 3) * LB + ul0] = m0.w;
        Mss[(dq + 0) * LB + ul1] = m1.x; Mss[(dq + 1) * LB + ul1] = m1.y;
        Mss[(dq + 2) * LB + ul1] = m1.z; Mss[(dq + 3) * LB + ul1] = m1.w;
        __syncthreads();
        if (c < 15) LOADD((c + 1) * 16);

#pragma unroll
        for (int kk = 0; kk < 16; kk++) {
            float la[8], lb[8];
            *(float4*)&la[0] = *(const float4*)&Qs[kk * LB + ty * 8];
            *(float4*)&la[4] = *(const float4*)&Qs[kk * LB + ty * 8 + 4];
            *(float4*)&lb[0] = *(const float4*)&Mss[kk * LB + tx * 8];
            *(float4*)&lb[4] = *(const float4*)&Mss[kk * LB + tx * 8 + 4];
#pragma unroll
            for (int a = 0; a < 8; a++)
#pragma unroll
                for (int cc = 0; cc < 8; cc++) acc[a][cc] = fmaf(la[a], lb[cc], acc[a][cc]);
        }
    }
#undef LOADD

#pragma unroll
    for (int a = 0; a < 8; a++) {
        const int u = uBase + ty * 8 + a;
        const size_t orow = ((size_t)(u >> 6) * LL + n * WW + (u & 63)) * DD;
        *(float4*)(out + orow + oBase + tx * 8)     = *(float4*)&acc[a][0];
        *(float4*)(out + orow + oBase + tx * 8 + 4) = *(float4*)&acc[a][4];
    }
}

// ---------------------------------------------------------------------------
extern "C" void kernel_launch(void* const* d_in, const int* in_sizes, int n_in,
                              void* d_out, int out_size) {
    const float* keys    = (const float*)d_in[0];
    const float* values  = (const float*)d_in[1];
    const float* queries = (const float*)d_in[2];
    const float* gammas  = (const float*)d_in[3];
    const float* alpha   = (const float*)d_in[4];
    float* out = (float*)d_out;

    (void)in_sizes; (void)n_in; (void)out_size;

    dim3 blk(16, 16);
    k_sums<<<dim3(2, 2, NW * 2), blk>>>(keys, values, gammas, alpha);
    k_scan<<<64, 512>>>();
    k_out<<<dim3(2, 4, NW), blk>>>(queries, out);
}

// round 5
// speedup vs baseline: 3.4779x; 1.5478x over previous
#include <cuda_runtime.h>
#include <math.h>

#define BB 8
#define LL 8192
#define DD 256
#define WW 64
#define NW 128
#define RW 512   /* B*W reduction rows per window */
#define LB 132   /* padded smem row stride (floats) */

// Scratch (allocation-free rule: static __device__ arrays)
__device__ float g_A[(size_t)NW * DD * DD];    // A_n = a*I - Skk_n   (32 MB)
__device__ float g_Svk[(size_t)NW * DD * DD];  // Svk_n               (32 MB)
__device__ float g_Ms[(size_t)NW * DD * DD];   // M snapshots         (32 MB)

// ---------------------------------------------------------------------------
// Kernel 1: per-window sums.
//   Skk_n[i,j] = sum_r g_r K_r[i] K_r[j];  Svk_n[i,j] = sum_r g_r V_r[i] K_r[j]
// grid (2, 2, NW*2): z even -> A (= aI - Skk), z odd -> Svk. block (16,16).
// 128x128 tile, 8x8 register tile, K-chunk 16.
// Double-buffered smem, ONE __syncthreads per chunk.
// ---------------------------------------------------------------------------
__global__ __launch_bounds__(256, 2) void k_sums(const float* __restrict__ keysp,
                                                 const float* __restrict__ values,
                                                 const float* __restrict__ gammas,
                                                 const float* __restrict__ alpha) {
    const int n    = blockIdx.z >> 1;
    const bool isA = (blockIdx.z & 1) == 0;
    const int jBase = blockIdx.x * 128;
    const int iBase = blockIdx.y * 128;
    const float* __restrict__ left = isA ? keysp : values;

    __shared__ float Ls[2][16 * LB];
    __shared__ float Rs[2][16 * LB];

    const int tx = threadIdx.x, ty = threadIdx.y;
    const int tid = ty * 16 + tx;
    const int row0 = tid >> 5;          // 0..7
    const int row1 = row0 + 8;          // 8..15
    const int c4   = (tid & 31) * 4;    // 0..124

    float acc[8][8];
#pragma unroll
    for (int a = 0; a < 8; a++)
#pragma unroll
        for (int b = 0; b < 8; b++) acc[a][b] = 0.f;

    float4 lA0, lA1, rA0, rA1;
    float g0v, g1v;

#define LOADC(R0) do {                                                          \
        const int gr0 = (R0) + row0, gr1 = (R0) + row1;                         \
        const size_t o0 = ((size_t)(gr0 >> 6) * LL + n * WW + (gr0 & 63)) * DD; \
        const size_t o1 = ((size_t)(gr1 >> 6) * LL + n * WW + (gr1 & 63)) * DD; \
        g0v = gammas[(gr0 >> 6) * LL + n * WW + (gr0 & 63)];                    \
        g1v = gammas[(gr1 >> 6) * LL + n * WW + (gr1 & 63)];                    \
        lA0 = *(const float4*)(left  + o0 + iBase + c4);                        \
        lA1 = *(const float4*)(left  + o1 + iBase + c4);                        \
        rA0 = *(const float4*)(keysp + o0 + jBase + c4);                        \
        rA1 = *(const float4*)(keysp + o1 + jBase + c4);                        \
    } while (0)

#define STOREC(BUF) do {                                                        \
        float4 t;                                                               \
        t = lA0; t.x *= g0v; t.y *= g0v; t.z *= g0v; t.w *= g0v;                \
        *(float4*)&Ls[BUF][row0 * LB + c4] = t;                                 \
        t = lA1; t.x *= g1v; t.y *= g1v; t.z *= g1v; t.w *= g1v;                \
        *(float4*)&Ls[BUF][row1 * LB + c4] = t;                                 \
        *(float4*)&Rs[BUF][row0 * LB + c4] = rA0;                               \
        *(float4*)&Rs[BUF][row1 * LB + c4] = rA1;                               \
    } while (0)

    LOADC(0);
    STOREC(0);
    LOADC(16);
    __syncthreads();

    for (int c = 0; c < 32; c++) {
        const int cur = c & 1;
        if (c < 31) STOREC(cur ^ 1);      // store chunk c+1 into idle buffer
        if (c < 30) LOADC((c + 2) * 16);  // prefetch chunk c+2 into registers

#pragma unroll
        for (int kk = 0; kk < 16; kk++) {
            float la[8], lb[8];
            *(float4*)&la[0] = *(const float4*)&Ls[cur][kk * LB + ty * 8];
            *(float4*)&la[4] = *(const float4*)&Ls[cur][kk * LB + ty * 8 + 4];
            *(float4*)&lb[0] = *(const float4*)&Rs[cur][kk * LB + tx * 8];
            *(float4*)&lb[4] = *(const float4*)&Rs[cur][kk * LB + tx * 8 + 4];
#pragma unroll
            for (int a = 0; a < 8; a++)
#pragma unroll
                for (int b = 0; b < 8; b++) acc[a][b] = fmaf(la[a], lb[b], acc[a][b]);
        }
        __syncthreads();
    }
#undef LOADC
#undef STOREC

    const float aSig = 1.f / (1.f + expf(-alpha[0]));
    float* dst = isA ? g_A : g_Svk;
    const size_t base = (size_t)n * DD * DD;
#pragma unroll
    for (int a = 0; a < 8; a++) {
        const int i = iBase + ty * 8 + a;
#pragma unroll
        for (int b = 0; b < 8; b++) {
            const int j = jBase + tx * 8 + b;
            float v = acc[a][b];
            if (isA) v = ((i == j) ? aSig : 0.f) - v;
            acc[a][b] = v;
        }
        *(float4*)(dst + base + (size_t)i * DD + jBase + tx * 8)     = *(float4*)&acc[a][0];
        *(float4*)(dst + base + (size_t)i * DD + jBase + tx * 8 + 4) = *(float4*)&acc[a][4];
    }
}

// ---------------------------------------------------------------------------
// Kernel 2: sequential scan, row-parallel.
//   M_n[r, j] = sum_d M_{n-1}[r, d] * A_n[d, j] + Svk_n[r, j]
// grid 64 CTAs x 4 rows, block 1024: thread = (j = t&255, h = t>>8 in 0..3).
// Each h-quarter covers 64 d's in 4 batches of 16, software-pipelined LDGs,
// d-sweep start staggered by blockIdx to decorrelate L2 slice traffic.
// ---------------------------------------------------------------------------
__global__ __launch_bounds__(1024) void k_scan() {
    __shared__ float Msm[4][DD];
    __shared__ float part[4][4][DD];   // [h][r][j]
    const int j = threadIdx.x & 255;
    const int h = threadIdx.x >> 8;    // 0..3
    const int r0 = blockIdx.x * 4;
    const int dBase = h * 64;
    const int b0 = blockIdx.x & 3;     // stagger offset

    if (h == 0) { Msm[0][j] = 0.f; Msm[1][j] = 0.f; Msm[2][j] = 0.f; Msm[3][j] = 0.f; }
    __syncthreads();

    for (int n = 0; n < NW; n++) {
        const float* __restrict__ A = g_A + (size_t)n * DD * DD;
        const float* __restrict__ S = g_Svk + (size_t)n * DD * DD + (size_t)r0 * DD;

        // Svk loads issued early (h==0 only), consumed at loop end
        float s0 = 0.f, s1 = 0.f, s2 = 0.f, s3 = 0.f;
        if (h == 0) { s0 = S[j]; s1 = S[DD + j]; s2 = S[2 * DD + j]; s3 = S[3 * DD + j]; }

        float t0 = 0.f, t1 = 0.f, t2 = 0.f, t3 = 0.f;
        float av[2][16];

        // prefetch batch 0
        {
            const int d0 = dBase + (b0 & 3) * 16;
#pragma unroll
            for (int k = 0; k < 16; k++) av[0][k] = A[(size_t)(d0 + k) * DD + j];
        }

#pragma unroll
        for (int bi = 0; bi < 4; bi++) {
            const int cur = bi & 1;
            const int d0 = dBase + ((b0 + bi) & 3) * 16;
            if (bi < 3) {
                const int d1 = dBase + ((b0 + bi + 1) & 3) * 16;
#pragma unroll
                for (int k = 0; k < 16; k++)
                    av[cur ^ 1][k] = A[(size_t)(d1 + k) * DD + j];
            }
#pragma unroll
            for (int k = 0; k < 16; k += 4) {
                const float4 m0 = *(const float4*)&Msm[0][d0 + k];
                const float4 m1 = *(const float4*)&Msm[1][d0 + k];
                const float4 m2 = *(const float4*)&Msm[2][d0 + k];
                const float4 m3 = *(const float4*)&Msm[3][d0 + k];
                t0 = fmaf(m0.x, av[cur][k], t0); t0 = fmaf(m0.y, av[cur][k + 1], t0);
                t0 = fmaf(m0.z, av[cur][k + 2], t0); t0 = fmaf(m0.w, av[cur][k + 3], t0);
                t1 = fmaf(m1.x, av[cur][k], t1); t1 = fmaf(m1.y, av[cur][k + 1], t1);
                t1 = fmaf(m1.z, av[cur][k + 2], t1); t1 = fmaf(m1.w, av[cur][k + 3], t1);
                t2 = fmaf(m2.x, av[cur][k], t2); t2 = fmaf(m2.y, av[cur][k + 1], t2);
                t2 = fmaf(m2.z, av[cur][k + 2], t2); t2 = fmaf(m2.w, av[cur][k + 3], t2);
                t3 = fmaf(m3.x, av[cur][k], t3); t3 = fmaf(m3.y, av[cur][k + 1], t3);
                t3 = fmaf(m3.z, av[cur][k + 2], t3); t3 = fmaf(m3.w, av[cur][k + 3], t3);
            }
        }

        if (h == 0) { t0 += s0; t1 += s1; t2 += s2; t3 += s3; }

        part[h][0][j] = t0; part[h][1][j] = t1; part[h][2][j] = t2; part[h][3][j] = t3;
        __syncthreads();

        // combine: quarter h owns row h
        const float u = part[0][h][j] + part[1][h][j] + part[2][h][j] + part[3][h][j];
        Msm[h][j] = u;
        g_Ms[(size_t)n * DD * DD + (size_t)(r0 + h) * DD + j] = u;
        __syncthreads();
    }
}

// ---------------------------------------------------------------------------
// Kernel 3: retrieval.  out[b, n*W+w, o] = sum_d Q[b, n*W+w, d] * Ms_n[o, d]
// grid (2, 4, NW). 128x128 tile, 8x8 register tile, double-buffered smem
// with one sync per 16-d chunk. Operands transposed into padded smem.
// ---------------------------------------------------------------------------
__global__ __launch_bounds__(256, 2) void k_out(const float* __restrict__ queries,
                                                float* __restrict__ out) {
    const int n = blockIdx.z;
    const int oBase = blockIdx.x * 128;
    const int uBase = blockIdx.y * 128;

    __shared__ float Qs[2][16 * LB];   // [d][u]
    __shared__ float Mss[2][16 * LB];  // [d][o]

    const int tx = threadIdx.x, ty = threadIdx.y;
    const int tid = ty * 16 + tx;
    const int ul0 = tid >> 2;         // 0..63
    const int ul1 = ul0 + 64;         // 64..127
    const int dq  = (tid & 3) * 4;    // 0,4,8,12

    const float* __restrict__ Mbase = g_Ms + (size_t)n * DD * DD;

    const int ug0 = uBase + ul0, ug1 = uBase + ul1;
    const size_t qoff0 = ((size_t)(ug0 >> 6) * LL + n * WW + (ug0 & 63)) * DD;
    const size_t qoff1 = ((size_t)(ug1 >> 6) * LL + n * WW + (ug1 & 63)) * DD;

    float acc[8][8];
#pragma unroll
    for (int a = 0; a < 8; a++)
#pragma unroll
        for (int c = 0; c < 8; c++) acc[a][c] = 0.f;

    float4 q0, q1, m0, m1;
#define LOADD(D0) do {                                                         \
        q0 = *(const float4*)(queries + qoff0 + (D0) + dq);                    \
        q1 = *(const float4*)(queries + qoff1 + (D0) + dq);                    \
        m0 = *(const float4*)(Mbase + (size_t)(oBase + ul0) * DD + (D0) + dq); \
        m1 = *(const float4*)(Mbase + (size_t)(oBase + ul1) * DD + (D0) + dq); \
    } while (0)

#define STORED(BUF) do {                                                       \
        Qs[BUF][(dq + 0) * LB + ul0] = q0.x; Qs[BUF][(dq + 1) * LB + ul0] = q0.y; \
        Qs[BUF][(dq + 2) * LB + ul0] = q0.z; Qs[BUF][(dq + 3) * LB + ul0] = q0.w; \
        Qs[BUF][(dq + 0) * LB + ul1] = q1.x; Qs[BUF][(dq + 1) * LB + ul1] = q1.y; \
        Qs[BUF][(dq + 2) * LB + ul1] = q1.z; Qs[BUF][(dq + 3) * LB + ul1] = q1.w; \
        Mss[BUF][(dq + 0) * LB + ul0] = m0.x; Mss[BUF][(dq + 1) * LB + ul0] = m0.y; \
        Mss[BUF][(dq + 2) * LB + ul0] = m0.z; Mss[BUF][(dq + 3) * LB + ul0] = m0.w; \
        Mss[BUF][(dq + 0) * LB + ul1] = m1.x; Mss[BUF][(dq + 1) * LB + ul1] = m1.y; \
        Mss[BUF][(dq + 2) * LB + ul1] = m1.z; Mss[BUF][(dq + 3) * LB + ul1] = m1.w; \
    } while (0)

    LOADD(0);
    STORED(0);
    LOADD(16);
    __syncthreads();

    for (int c = 0; c < 16; c++) {
        const int cur = c & 1;
        if (c < 15) STORED(cur ^ 1);
        if (c < 14) LOADD((c + 2) * 16);

#pragma unroll
        for (int kk = 0; kk < 16; kk++) {
            float la[8], lb[8];
            *(float4*)&la[0] = *(const float4*)&Qs[cur][kk * LB + ty * 8];
            *(float4*)&la[4] = *(const float4*)&Qs[cur][kk * LB + ty * 8 + 4];
            *(float4*)&lb[0] = *(const float4*)&Mss[cur][kk * LB + tx * 8];
            *(float4*)&lb[4] = *(const float4*)&Mss[cur][kk * LB + tx * 8 + 4];
#pragma unroll
            for (int a = 0; a < 8; a++)
#pragma unroll
                for (int cc = 0; cc < 8; cc++) acc[a][cc] = fmaf(la[a], lb[cc], acc[a][cc]);
        }
        __syncthreads();
    }
#undef LOADD
#undef STORED

#pragma unroll
    for (int a = 0; a < 8; a++) {
        const int u = uBase + ty * 8 + a;
        const size_t orow = ((size_t)(u >> 6) * LL + n * WW + (u & 63)) * DD;
        *(float4*)(out + orow + oBase + tx * 8)     = *(float4*)&acc[a][0];
        *(float4*)(out + orow + oBase + tx * 8 + 4) = *(float4*)&acc[a][4];
    }
}

// ---------------------------------------------------------------------------
extern "C" void kernel_launch(void* const* d_in, const int* in_sizes, int n_in,
                              void* d_out, int out_size) {
    const float* keys    = (const float*)d_in[0];
    const float* values  = (const float*)d_in[1];
    const float* queries = (const float*)d_in[2];
    const float* gammas  = (const float*)d_in[3];
    const float* alpha   = (const float*)d_in[4];
    float* out = (float*)d_out;

    (void)in_sizes; (void)n_in; (void)out_size;

    dim3 blk(16, 16);
    k_sums<<<dim3(2, 2, NW * 2), blk>>>(keys, values, gammas, alpha);
    k_scan<<<64, 1024>>>();
    k_out<<<dim3(2, 4, NW), blk>>>(queries, out);
}

// round 6
// speedup vs baseline: 4.1395x; 1.1902x over previous
#include <cuda_runtime.h>
#include <math.h>
#include <cstdint>

#define BB 8
#define LL 8192
#define DD 256
#define WW 64
#define NW 128
#define RW 512   /* B*W reduction rows per window */
#define LB 132   /* padded smem row stride (floats) */

// Scratch (allocation-free rule: static __device__ arrays)
__device__ float g_A[(size_t)NW * DD * DD];    // A_n = a*I - Skk_n   (32 MB)
__device__ float g_Svk[(size_t)NW * DD * DD];  // Svk_n               (32 MB)
__device__ float g_Ms[(size_t)NW * DD * DD];   // M snapshots         (32 MB)

// ---------------------------------------------------------------------------
// Kernel 1: per-window sums (unchanged from round 5).
// ---------------------------------------------------------------------------
__global__ __launch_bounds__(256, 2) void k_sums(const float* __restrict__ keysp,
                                                 const float* __restrict__ values,
                                                 const float* __restrict__ gammas,
                                                 const float* __restrict__ alpha) {
    const int n    = blockIdx.z >> 1;
    const bool isA = (blockIdx.z & 1) == 0;
    const int jBase = blockIdx.x * 128;
    const int iBase = blockIdx.y * 128;
    const float* __restrict__ left = isA ? keysp : values;

    __shared__ float Ls[2][16 * LB];
    __shared__ float Rs[2][16 * LB];

    const int tx = threadIdx.x, ty = threadIdx.y;
    const int tid = ty * 16 + tx;
    const int row0 = tid >> 5;
    const int row1 = row0 + 8;
    const int c4   = (tid & 31) * 4;

    float acc[8][8];
#pragma unroll
    for (int a = 0; a < 8; a++)
#pragma unroll
        for (int b = 0; b < 8; b++) acc[a][b] = 0.f;

    float4 lA0, lA1, rA0, rA1;
    float g0v, g1v;

#define LOADC(R0) do {                                                          \
        const int gr0 = (R0) + row0, gr1 = (R0) + row1;                         \
        const size_t o0 = ((size_t)(gr0 >> 6) * LL + n * WW + (gr0 & 63)) * DD; \
        const size_t o1 = ((size_t)(gr1 >> 6) * LL + n * WW + (gr1 & 63)) * DD; \
        g0v = gammas[(gr0 >> 6) * LL + n * WW + (gr0 & 63)];                    \
        g1v = gammas[(gr1 >> 6) * LL + n * WW + (gr1 & 63)];                    \
        lA0 = *(const float4*)(left  + o0 + iBase + c4);                        \
        lA1 = *(const float4*)(left  + o1 + iBase + c4);                        \
        rA0 = *(const float4*)(keysp + o0 + jBase + c4);                        \
        rA1 = *(const float4*)(keysp + o1 + jBase + c4);                        \
    } while (0)

#define STOREC(BUF) do {                                                        \
        float4 t;                                                               \
        t = lA0; t.x *= g0v; t.y *= g0v; t.z *= g0v; t.w *= g0v;                \
        *(float4*)&Ls[BUF][row0 * LB + c4] = t;                                 \
        t = lA1; t.x *= g1v; t.y *= g1v; t.z *= g1v; t.w *= g1v;                \
        *(float4*)&Ls[BUF][row1 * LB + c4] = t;                                 \
        *(float4*)&Rs[BUF][row0 * LB + c4] = rA0;                               \
        *(float4*)&Rs[BUF][row1 * LB + c4] = rA1;                               \
    } while (0)

    LOADC(0);
    STOREC(0);
    LOADC(16);
    __syncthreads();

    for (int c = 0; c < 32; c++) {
        const int cur = c & 1;
        if (c < 31) STOREC(cur ^ 1);
        if (c < 30) LOADC((c + 2) * 16);

#pragma unroll
        for (int kk = 0; kk < 16; kk++) {
            float la[8], lb[8];
            *(float4*)&la[0] = *(const float4*)&Ls[cur][kk * LB + ty * 8];
            *(float4*)&la[4] = *(const float4*)&Ls[cur][kk * LB + ty * 8 + 4];
            *(float4*)&lb[0] = *(const float4*)&Rs[cur][kk * LB + tx * 8];
            *(float4*)&lb[4] = *(const float4*)&Rs[cur][kk * LB + tx * 8 + 4];
#pragma unroll
            for (int a = 0; a < 8; a++)
#pragma unroll
                for (int b = 0; b < 8; b++) acc[a][b] = fmaf(la[a], lb[b], acc[a][b]);
        }
        __syncthreads();
    }
#undef LOADC
#undef STOREC

    const float aSig = 1.f / (1.f + expf(-alpha[0]));
    float* dst = isA ? g_A : g_Svk;
    const size_t base = (size_t)n * DD * DD;
#pragma unroll
    for (int a = 0; a < 8; a++) {
        const int i = iBase + ty * 8 + a;
#pragma unroll
        for (int b = 0; b < 8; b++) {
            const int j = jBase + tx * 8 + b;
            float v = acc[a][b];
            if (isA) v = ((i == j) ? aSig : 0.f) - v;
            acc[a][b] = v;
        }
        *(float4*)(dst + base + (size_t)i * DD + jBase + tx * 8)     = *(float4*)&acc[a][0];
        *(float4*)(dst + base + (size_t)i * DD + jBase + tx * 8 + 4) = *(float4*)&acc[a][4];
    }
}

// ---------------------------------------------------------------------------
// Kernel 2: sequential scan, cluster-pair column split.
//   M_n[r, j] = sum_d M_{n-1}[r, d] * A_n[d, j] + Svk_n[r, j]
// grid 128 CTAs (64 clusters of 2), block 512.
// Cluster pair p handles rows [4p, 4p+4); rank = column half (128 cols).
// Msm4[buf][d] = float4 of M rows r0..r0+3 at column d (double buffered).
// Each CTA writes its computed half into BOTH its own and its partner's
// next-buffer Msm4 (DSMEM), one cluster barrier per window.
// Thread: jg = t&31 (4 cols), hq = t>>5 (16 d's). All LDG.128.
// ---------------------------------------------------------------------------
__global__ __launch_bounds__(512) __cluster_dims__(2, 1, 1) void k_scan() {
    __shared__ float4 Msm4[2][DD];          // 8 KB
    __shared__ float part[16][4][128];      // 32 KB

    const int t = threadIdx.x;
    const int jg = t & 31;
    const int hq = t >> 5;                  // 0..15
    const int dBase = hq * 16;

    uint32_t rank;
    asm("mov.u32 %0, %%cluster_ctarank;" : "=r"(rank));
    const uint32_t prank = rank ^ 1u;
    const int ch = (int)rank;               // column half
    const int r0 = (blockIdx.x >> 1) * 4;   // row group
    const int j4 = ch * 128 + jg * 4;

    // combine-phase mapping
    const int rr  = t >> 7;                 // 0..3
    const int jl  = t & 127;                // 0..127
    const int jgl = ch * 128 + jl;          // global column

    // zero buffer 0
    if (t < DD) Msm4[0][t] = make_float4(0.f, 0.f, 0.f, 0.f);
    __syncthreads();

    // local smem address of Msm4 as u32 (for mapa)
    uint32_t msmBase;
    {
        uint64_t tmp;
        asm("cvta.to.shared.u64 %0, %1;" : "=l"(tmp) : "l"((const void*)&Msm4[0][0]));
        msmBase = (uint32_t)tmp;
    }

    float4 avA[8];
    // prefetch window 0, batch 0 (d = dBase .. dBase+7)
#pragma unroll
    for (int d = 0; d < 8; d++)
        avA[d] = *(const float4*)(g_A + (size_t)(dBase + d) * DD + j4);

    for (int n = 0; n < NW; n++) {
        const float* __restrict__ A = g_A + (size_t)n * DD * DD;
        const int cur = n & 1;
        const int nb  = cur ^ 1;

        // batch 1 loads (d = dBase+8 .. dBase+15)
        float4 avB[8];
#pragma unroll
        for (int d = 0; d < 8; d++)
            avB[d] = *(const float4*)(A + (size_t)(dBase + 8 + d) * DD + j4);

        float4 a0 = {0,0,0,0}, a1 = {0,0,0,0}, a2 = {0,0,0,0}, a3 = {0,0,0,0};
#pragma unroll
        for (int d = 0; d < 8; d++) {
            const float4 m = Msm4[cur][dBase + d];
            const float4 a = avA[d];
            a0.x = fmaf(m.x, a.x, a0.x); a0.y = fmaf(m.x, a.y, a0.y);
            a0.z = fmaf(m.x, a.z, a0.z); a0.w = fmaf(m.x, a.w, a0.w);
            a1.x = fmaf(m.y, a.x, a1.x); a1.y = fmaf(m.y, a.y, a1.y);
            a1.z = fmaf(m.y, a.z, a1.z); a1.w = fmaf(m.y, a.w, a1.w);
            a2.x = fmaf(m.z, a.x, a2.x); a2.y = fmaf(m.z, a.y, a2.y);
            a2.z = fmaf(m.z, a.z, a2.z); a2.w = fmaf(m.z, a.w, a2.w);
            a3.x = fmaf(m.w, a.x, a3.x); a3.y = fmaf(m.w, a.y, a3.y);
            a3.z = fmaf(m.w, a.z, a3.z); a3.w = fmaf(m.w, a.w, a3.w);
        }
#pragma unroll
        for (int d = 0; d < 8; d++) {
            const float4 m = Msm4[cur][dBase + 8 + d];
            const float4 a = avB[d];
            a0.x = fmaf(m.x, a.x, a0.x); a0.y = fmaf(m.x, a.y, a0.y);
            a0.z = fmaf(m.x, a.z, a0.z); a0.w = fmaf(m.x, a.w, a0.w);
            a1.x = fmaf(m.y, a.x, a1.x); a1.y = fmaf(m.y, a.y, a1.y);
            a1.z = fmaf(m.y, a.z, a1.z); a1.w = fmaf(m.y, a.w, a1.w);
            a2.x = fmaf(m.z, a.x, a2.x); a2.y = fmaf(m.z, a.y, a2.y);
            a2.z = fmaf(m.z, a.z, a2.z); a2.w = fmaf(m.z, a.w, a2.w);
            a3.x = fmaf(m.w, a.x, a3.x); a3.y = fmaf(m.w, a.y, a3.y);
            a3.z = fmaf(m.w, a.z, a3.z); a3.w = fmaf(m.w, a.w, a3.w);
        }

        *(float4*)&part[hq][0][jg * 4] = a0;
        *(float4*)&part[hq][1][jg * 4] = a1;
        *(float4*)&part[hq][2][jg * 4] = a2;
        *(float4*)&part[hq][3][jg * 4] = a3;

        // prefetch next window batch 0 (independent of all sync below)
        if (n < NW - 1) {
            const float* __restrict__ An = g_A + (size_t)(n + 1) * DD * DD;
#pragma unroll
            for (int d = 0; d < 8; d++)
                avA[d] = *(const float4*)(An + (size_t)(dBase + d) * DD + j4);
        }
        __syncthreads();

        // combine: one scalar (rr, jgl) per thread
        float sval = g_Svk[(size_t)n * DD * DD + (size_t)(r0 + rr) * DD + jgl];
        float u = 0.f;
#pragma unroll
        for (int q = 0; q < 16; q++) u += part[q][rr][jl];
        u += sval;

        // write my half into my own next buffer + partner's next buffer
        const uint32_t off = (uint32_t)(nb * DD * 16 + (jgl * 4 + rr) * 4);
        const uint32_t laddr = msmBase + off;
        asm volatile("st.shared.f32 [%0], %1;" :: "r"(laddr), "f"(u));
        uint32_t raddr;
        asm("mapa.shared::cluster.u32 %0, %1, %2;" : "=r"(raddr) : "r"(laddr), "r"(prank));
        asm volatile("st.shared::cluster.f32 [%0], %1;" :: "r"(raddr), "f"(u));

        // snapshot
        g_Ms[(size_t)n * DD * DD + (size_t)(r0 + rr) * DD + jgl] = u;

        asm volatile("barrier.cluster.arrive.aligned;" ::: "memory");
        asm volatile("barrier.cluster.wait.aligned;" ::: "memory");
    }
}

// ---------------------------------------------------------------------------
// Kernel 3: retrieval (unchanged from round 5).
// ---------------------------------------------------------------------------
__global__ __launch_bounds__(256, 2) void k_out(const float* __restrict__ queries,
                                                float* __restrict__ out) {
    const int n = blockIdx.z;
    const int oBase = blockIdx.x * 128;
    const int uBase = blockIdx.y * 128;

    __shared__ float Qs[2][16 * LB];
    __shared__ float Mss[2][16 * LB];

    const int tx = threadIdx.x, ty = threadIdx.y;
    const int tid = ty * 16 + tx;
    const int ul0 = tid >> 2;
    const int ul1 = ul0 + 64;
    const int dq  = (tid & 3) * 4;

    const float* __restrict__ Mbase = g_Ms + (size_t)n * DD * DD;

    const int ug0 = uBase + ul0, ug1 = uBase + ul1;
    const size_t qoff0 = ((size_t)(ug0 >> 6) * LL + n * WW + (ug0 & 63)) * DD;
    const size_t qoff1 = ((size_t)(ug1 >> 6) * LL + n * WW + (ug1 & 63)) * DD;

    float acc[8][8];
#pragma unroll
    for (int a = 0; a < 8; a++)
#pragma unroll
        for (int c = 0; c < 8; c++) acc[a][c] = 0.f;

    float4 q0, q1, m0, m1;
#define LOADD(D0) do {                                                         \
        q0 = *(const float4*)(queries + qoff0 + (D0) + dq);                    \
        q1 = *(const float4*)(queries + qoff1 + (D0) + dq);                    \
        m0 = *(const float4*)(Mbase + (size_t)(oBase + ul0) * DD + (D0) + dq); \
        m1 = *(const float4*)(Mbase + (size_t)(oBase + ul1) * DD + (D0) + dq); \
    } while (0)

#define STORED(BUF) do {                                                       \
        Qs[BUF][(dq + 0) * LB + ul0] = q0.x; Qs[BUF][(dq + 1) * LB + ul0] = q0.y; \
        Qs[BUF][(dq + 2) * LB + ul0] = q0.z; Qs[BUF][(dq + 3) * LB + ul0] = q0.w; \
        Qs[BUF][(dq + 0) * LB + ul1] = q1.x; Qs[BUF][(dq + 1) * LB + ul1] = q1.y; \
        Qs[BUF][(dq + 2) * LB + ul1] = q1.z; Qs[BUF][(dq + 3) * LB + ul1] = q1.w; \
        Mss[BUF][(dq + 0) * LB + ul0] = m0.x; Mss[BUF][(dq + 1) * LB + ul0] = m0.y; \
        Mss[BUF][(dq + 2) * LB + ul0] = m0.z; Mss[BUF][(dq + 3) * LB + ul0] = m0.w; \
        Mss[BUF][(dq + 0) * LB + ul1] = m1.x; Mss[BUF][(dq + 1) * LB + ul1] = m1.y; \
        Mss[BUF][(dq + 2) * LB + ul1] = m1.z; Mss[BUF][(dq + 3) * LB + ul1] = m1.w; \
    } while (0)

    LOADD(0);
    STORED(0);
    LOADD(16);
    __syncthreads();

    for (int c = 0; c < 16; c++) {
        const int cur = c & 1;
        if (c < 15) STORED(cur ^ 1);
        if (c < 14) LOADD((c + 2) * 16);

#pragma unroll
        for (int kk = 0; kk < 16; kk++) {
            float la[8], lb[8];
            *(float4*)&la[0] = *(const float4*)&Qs[cur][kk * LB + ty * 8];
            *(float4*)&la[4] = *(const float4*)&Qs[cur][kk * LB + ty * 8 + 4];
            *(float4*)&lb[0] = *(const float4*)&Mss[cur][kk * LB + tx * 8];
            *(float4*)&lb[4] = *(const float4*)&Mss[cur][kk * LB + tx * 8 + 4];
#pragma unroll
            for (int a = 0; a < 8; a++)
#pragma unroll
                for (int cc = 0; cc < 8; cc++) acc[a][cc] = fmaf(la[a], lb[cc], acc[a][cc]);
        }
        __syncthreads();
    }
#undef LOADD
#undef STORED

#pragma unroll
    for (int a = 0; a < 8; a++) {
        const int u = uBase + ty * 8 + a;
        const size_t orow = ((size_t)(u >> 6) * LL + n * WW + (u & 63)) * DD;
        *(float4*)(out + orow + oBase + tx * 8)     = *(float4*)&acc[a][0];
        *(float4*)(out + orow + oBase + tx * 8 + 4) = *(float4*)&acc[a][4];
    }
}

// ---------------------------------------------------------------------------
extern "C" void kernel_launch(void* const* d_in, const int* in_sizes, int n_in,
                              void* d_out, int out_size) {
    const float* keys    = (const float*)d_in[0];
    const float* values  = (const float*)d_in[1];
    const float* queries = (const float*)d_in[2];
    const float* gammas  = (const float*)d_in[3];
    const float* alpha   = (const float*)d_in[4];
    float* out = (float*)d_out;

    (void)in_sizes; (void)n_in; (void)out_size;

    dim3 blk(16, 16);
    k_sums<<<dim3(2, 2, NW * 2), blk>>>(keys, values, gammas, alpha);
    k_scan<<<128, 512>>>();
    k_out<<<dim3(2, 4, NW), blk>>>(queries, out);
}

// round 9
// speedup vs baseline: 4.5698x; 1.1039x over previous
#include <cuda_runtime.h>
#include <math.h>
#include <cstdint>

#define BB 8
#define LL 8192
#define DD 256
#define WW 64
#define NW 128
#define RW 512   /* B*W reduction rows per window */
#define LB 132   /* padded smem row stride (floats) */

// Scratch (allocation-free rule: static __device__ arrays)
__device__ float g_A[(size_t)NW * DD * DD];    // A_n = a*I - Skk_n   (32 MB)
__device__ float g_Svk[(size_t)NW * DD * DD];  // Svk_n               (32 MB)
__device__ float g_Ms[(size_t)NW * DD * DD];   // M snapshots         (32 MB)

// ---- packed fp32x2 helpers (FFMA2) ----------------------------------------
__device__ __forceinline__ uint64_t pk2(float x) {
    uint64_t r; asm("mov.b64 %0, {%1, %1};" : "=l"(r) : "f"(x)); return r;
}
__device__ __forceinline__ uint64_t pkxy(float x, float y) {
    uint64_t r; asm("mov.b64 %0, {%1, %2};" : "=l"(r) : "f"(x), "f"(y)); return r;
}
__device__ __forceinline__ void fma2(uint64_t& d, uint64_t a, uint64_t b) {
    asm("fma.rn.f32x2 %0, %1, %2, %3;" : "=l"(d) : "l"(a), "l"(b), "l"(d));
}
__device__ __forceinline__ float2 up2(uint64_t p) {
    float2 r; asm("mov.b64 {%0, %1}, %2;" : "=f"(r.x), "=f"(r.y) : "l"(p)); return r;
}

// ---------------------------------------------------------------------------
// Kernel 1: per-window sums, FFMA2 inner loop.
//   Skk_n[i,j] = sum_r g_r K_r[i] K_r[j];  Svk_n[i,j] = sum_r g_r V_r[i] K_r[j]
// grid (2, 2, NW*2): z even -> A (= aI - Skk), z odd -> Svk. block (16,16).
// 128x128 tile, 8x8 register tile (as 8x4 f32x2 pairs), K-chunk 16,
// double-buffered smem, one __syncthreads per chunk.
// ---------------------------------------------------------------------------
__global__ __launch_bounds__(256, 2) void k_sums(const float* __restrict__ keysp,
                                                 const float* __restrict__ values,
                                                 const float* __restrict__ gammas,
                                                 const float* __restrict__ alpha) {
    const int n    = blockIdx.z >> 1;
    const bool isA = (blockIdx.z & 1) == 0;
    const int jBase = blockIdx.x * 128;
    const int iBase = blockIdx.y * 128;
    const float* __restrict__ left = isA ? keysp : values;

    __shared__ float Ls[2][16 * LB];
    __shared__ float Rs[2][16 * LB];

    const int tx = threadIdx.x, ty = threadIdx.y;
    const int tid = ty * 16 + tx;
    const int row0 = tid >> 5;
    const int row1 = row0 + 8;
    const int c4   = (tid & 31) * 4;

    uint64_t acc2[8][4];
#pragma unroll
    for (int a = 0; a < 8; a++)
#pragma unroll
        for (int b = 0; b < 4; b++) acc2[a][b] = 0ull;

    float4 lA0, lA1, rA0, rA1;
    float g0v, g1v;

#define LOADC(R0) do {                                                          \
        const int gr0 = (R0) + row0, gr1 = (R0) + row1;                         \
        const size_t o0 = ((size_t)(gr0 >> 6) * LL + n * WW + (gr0 & 63)) * DD; \
        const size_t o1 = ((size_t)(gr1 >> 6) * LL + n * WW + (gr1 & 63)) * DD; \
        g0v = gammas[(gr0 >> 6) * LL + n * WW + (gr0 & 63)];                    \
        g1v = gammas[(gr1 >> 6) * LL + n * WW + (gr1 & 63)];                    \
        lA0 = *(const float4*)(left  + o0 + iBase + c4);                        \
        lA1 = *(const float4*)(left  + o1 + iBase + c4);                        \
        rA0 = *(const float4*)(keysp + o0 + jBase + c4);                        \
        rA1 = *(const float4*)(keysp + o1 + jBase + c4);                        \
    } while (0)

#define STOREC(BUF) do {                                                        \
        float4 t;                                                               \
        t = lA0; t.x *= g0v; t.y *= g0v; t.z *= g0v; t.w *= g0v;                \
        *(float4*)&Ls[BUF][row0 * LB + c4] = t;                                 \
        t = lA1; t.x *= g1v; t.y *= g1v; t.z *= g1v; t.w *= g1v;                \
        *(float4*)&Ls[BUF][row1 * LB + c4] = t;                                 \
        *(float4*)&Rs[BUF][row0 * LB + c4] = rA0;                               \
        *(float4*)&Rs[BUF][row1 * LB + c4] = rA1;                               \
    } while (0)

    LOADC(0);
    STOREC(0);
    LOADC(16);
    __syncthreads();

    for (int c = 0; c < 32; c++) {
        const int cur = c & 1;
        if (c < 31) STOREC(cur ^ 1);
        if (c < 30) LOADC((c + 2) * 16);

#pragma unroll
        for (int kk = 0; kk < 16; kk++) {
            float4 la0 = *(const float4*)&Ls[cur][kk * LB + ty * 8];
            float4 la1 = *(const float4*)&Ls[cur][kk * LB + ty * 8 + 4];
            float4 lb0 = *(const float4*)&Rs[cur][kk * LB + tx * 8];
            float4 lb1 = *(const float4*)&Rs[cur][kk * LB + tx * 8 + 4];
            uint64_t bp[4];
            bp[0] = pkxy(lb0.x, lb0.y); bp[1] = pkxy(lb0.z, lb0.w);
            bp[2] = pkxy(lb1.x, lb1.y); bp[3] = pkxy(lb1.z, lb1.w);
            float laf[8] = {la0.x, la0.y, la0.z, la0.w, la1.x, la1.y, la1.z, la1.w};
#pragma unroll
            for (int a = 0; a < 8; a++) {
                const uint64_t ap = pk2(laf[a]);
                fma2(acc2[a][0], ap, bp[0]);
                fma2(acc2[a][1], ap, bp[1]);
                fma2(acc2[a][2], ap, bp[2]);
                fma2(acc2[a][3], ap, bp[3]);
            }
        }
        __syncthreads();
    }
#undef LOADC
#undef STOREC

    const float aSig = 1.f / (1.f + expf(-alpha[0]));
    float* dst = isA ? g_A : g_Svk;
    const size_t base = (size_t)n * DD * DD;
#pragma unroll
    for (int a = 0; a < 8; a++) {
        const int i = iBase + ty * 8 + a;
        float f[8];
        float2 p;
        p = up2(acc2[a][0]); f[0] = p.x; f[1] = p.y;
        p = up2(acc2[a][1]); f[2] = p.x; f[3] = p.y;
        p = up2(acc2[a][2]); f[4] = p.x; f[5] = p.y;
        p = up2(acc2[a][3]); f[6] = p.x; f[7] = p.y;
#pragma unroll
        for (int b = 0; b < 8; b++) {
            const int j = jBase + tx * 8 + b;
            if (isA) f[b] = ((i == j) ? aSig : 0.f) - f[b];
        }
        *(float4*)(dst + base + (size_t)i * DD + jBase + tx * 8)     = *(float4*)&f[0];
        *(float4*)(dst + base + (size_t)i * DD + jBase + tx * 8 + 4) = *(float4*)&f[4];
    }
}

// ---------------------------------------------------------------------------
// Kernel 2: sequential scan, cluster-pair column split + mbarrier exchange.
//   M_n[r, j] = sum_d M_{n-1}[r, d] * A_n[d, j] + Svk_n[r, j]
// grid 128 CTAs (64 clusters of 2), block 512.
// Cluster pair handles rows [4p, 4p+4); rank = column half (128 cols).
// Per window: compute partials, combine, store own half locally + into the
// partner's next buffer (st.shared::cluster), then remote
// mbarrier.arrive.release.cluster (512 arrivals). Wait = try_wait.acquire.
// Both A half-batches for window n+1 prefetched; Svk load hoisted.
// ---------------------------------------------------------------------------
__global__ __launch_bounds__(512) __cluster_dims__(2, 1, 1) void k_scan() {
    __shared__ float4 Msm4[2][DD];          // 8 KB: [buf][global col] rows r0..r0+3
    __shared__ float part[16][4][128];      // 32 KB
    __shared__ uint64_t mbar[2];

    const int t = threadIdx.x;
    const int jg = t & 31;
    const int hq = t >> 5;                  // 0..15
    const int dBase = hq * 16;

    uint32_t rank;
    asm("mov.u32 %0, %%cluster_ctarank;" : "=r"(rank));
    const uint32_t prank = rank ^ 1u;
    const int ch = (int)rank;
    const int r0 = (blockIdx.x >> 1) * 4;
    const int j4 = ch * 128 + jg * 4;

    const int rr  = t >> 7;                 // 0..3
    const int jl  = t & 127;                // 0..127
    const int jgl = ch * 128 + jl;

    if (t < DD) Msm4[0][t] = make_float4(0.f, 0.f, 0.f, 0.f);
    if (t < 2) {
        uint32_t mb;
        {
            uint64_t tmp;
            asm("cvta.to.shared.u64 %0, %1;" : "=l"(tmp) : "l"((const void*)&mbar[t]));
            mb = (uint32_t)tmp;
        }
        asm volatile("mbarrier.init.shared.b64 [%0], %1;" :: "r"(mb), "r"(512u) : "memory");
    }
    __syncthreads();
    asm volatile("barrier.cluster.arrive.aligned;" ::: "memory");
    asm volatile("barrier.cluster.wait.aligned;" ::: "memory");

    uint32_t msmBase, mbarBase;
    {
        uint64_t tmp;
        asm("cvta.to.shared.u64 %0, %1;" : "=l"(tmp) : "l"((const void*)&Msm4[0][0]));
        msmBase = (uint32_t)tmp;
        asm("cvta.to.shared.u64 %0, %1;" : "=l"(tmp) : "l"((const void*)&mbar[0]));
        mbarBase = (uint32_t)tmp;
    }

    float4 avA[8], avB[8];
#pragma unroll
    for (int d = 0; d < 8; d++) {
        avA[d] = *(const float4*)(g_A + (size_t)(dBase + d) * DD + j4);
        avB[d] = *(const float4*)(g_A + (size_t)(dBase + 8 + d) * DD + j4);
    }

    for (int n = 0; n < NW; n++) {
        const int cur = n & 1;
        const int nb  = cur ^ 1;
        const uint32_t par = (uint32_t)((n >> 1) & 1);

        // hoisted Svk load (latency hidden under FMA stage)
        const float sval = g_Svk[(size_t)n * DD * DD + (size_t)(r0 + rr) * DD + jgl];

        float4 a0 = {0,0,0,0}, a1 = {0,0,0,0}, a2 = {0,0,0,0}, a3 = {0,0,0,0};
#pragma unroll
        for (int d = 0; d < 8; d++) {
            const float4 m = Msm4[cur][dBase + d];
            const float4 a = avA[d];
            a0.x = fmaf(m.x, a.x, a0.x); a0.y = fmaf(m.x, a.y, a0.y);
            a0.z = fmaf(m.x, a.z, a0.z); a0.w = fmaf(m.x, a.w, a0.w);
            a1.x = fmaf(m.y, a.x, a1.x); a1.y = fmaf(m.y, a.y, a1.y);
            a1.z = fmaf(m.y, a.z, a1.z); a1.w = fmaf(m.y, a.w, a1.w);
            a2.x = fmaf(m.z, a.x, a2.x); a2.y = fmaf(m.z, a.y, a2.y);
            a2.z = fmaf(m.z, a.z, a2.z); a2.w = fmaf(m.z, a.w, a2.w);
            a3.x = fmaf(m.w, a.x, a3.x); a3.y = fmaf(m.w, a.y, a3.y);
            a3.z = fmaf(m.w, a.z, a3.z); a3.w = fmaf(m.w, a.w, a3.w);
        }
#pragma unroll
        for (int d = 0; d < 8; d++) {
            const float4 m = Msm4[cur][dBase + 8 + d];
            const float4 a = avB[d];
            a0.x = fmaf(m.x, a.x, a0.x); a0.y = fmaf(m.x, a.y, a0.y);
            a0.z = fmaf(m.x, a.z, a0.z); a0.w = fmaf(m.x, a.w, a0.w);
            a1.x = fmaf(m.y, a.x, a1.x); a1.y = fmaf(m.y, a.y, a1.y);
            a1.z = fmaf(m.y, a.z, a1.z); a1.w = fmaf(m.y, a.w, a1.w);
            a2.x = fmaf(m.z, a.x, a2.x); a2.y = fmaf(m.z, a.y, a2.y);
            a2.z = fmaf(m.z, a.z, a2.z); a2.w = fmaf(m.z, a.w, a2.w);
            a3.x = fmaf(m.w, a.x, a3.x); a3.y = fmaf(m.w, a.y, a3.y);
            a3.z = fmaf(m.w, a.z, a3.z); a3.w = fmaf(m.w, a.w, a3.w);
        }

        *(float4*)&part[hq][0][jg * 4] = a0;
        *(float4*)&part[hq][1][jg * 4] = a1;
        *(float4*)&part[hq][2][jg * 4] = a2;
        *(float4*)&part[hq][3][jg * 4] = a3;

        // prefetch BOTH half-batches of next window's A (no dependence on sync)
        if (n < NW - 1) {
            const float* __restrict__ An = g_A + (size_t)(n + 1) * DD * DD;
#pragma unroll
            for (int d = 0; d < 8; d++) {
                avA[d] = *(const float4*)(An + (size_t)(dBase + d) * DD + j4);
                avB[d] = *(const float4*)(An + (size_t)(dBase + 8 + d) * DD + j4);
            }
        }
        __syncthreads();

        float u = 0.f;
#pragma unroll
        for (int q = 0; q < 16; q++) u += part[q][rr][jl];
        u += sval;

        // write own half into local next buffer + partner's next buffer
        const uint32_t off = (uint32_t)(nb * DD * 16 + (jgl * 4 + rr) * 4);
        const uint32_t laddr = msmBase + off;
        asm volatile("st.shared.f32 [%0], %1;" :: "r"(laddr), "f"(u));
        {
            uint32_t raddr;
            asm("mapa.shared::cluster.u32 %0, %1, %2;" : "=r"(raddr) : "r"(laddr), "r"(prank));
            asm volatile("st.shared::cluster.f32 [%0], %1;" :: "r"(raddr), "f"(u));
            uint32_t rmbar;
            asm("mapa.shared::cluster.u32 %0, %1, %2;"
                : "=r"(rmbar) : "r"(mbarBase + (uint32_t)(nb * 8)), "r"(prank));
            asm volatile("mbarrier.arrive.release.cluster.shared::cluster.b64 _, [%0];"
                         :: "r"(rmbar) : "memory");
        }

        g_Ms[(size_t)n * DD * DD + (size_t)(r0 + rr) * DD + jgl] = u;

        __syncthreads();   // local Msm[nb] stores visible CTA-wide

        // wait for partner's 512 arrivals (acquire orders its DSMEM stores)
        asm volatile(
            "{\n\t"
            ".reg .pred P;\n\t"
            "KSW_%=:\n\t"
            "mbarrier.try_wait.parity.acquire.cluster.shared::cta.b64 P, [%0], %1, 0x989680;\n\t"
            "@!P bra KSW_%=;\n\t"
            "}"
            :: "r"(mbarBase + (uint32_t)(nb * 8)), "r"(par) : "memory");
    }

    asm volatile("barrier.cluster.arrive.aligned;" ::: "memory");
    asm volatile("barrier.cluster.wait.aligned;" ::: "memory");
}

// ---------------------------------------------------------------------------
// Kernel 3: retrieval, FFMA2 inner loop.
//   out[b, n*W+w, o] = sum_d Q[b, n*W+w, d] * Ms_n[o, d]
// grid (2, 4, NW). 128x128 tile, 8x8 register tile (8x4 f32x2 pairs),
// double-buffered smem with one sync per 16-d chunk.
// ---------------------------------------------------------------------------
__global__ __launch_bounds__(256, 2) void k_out(const float* __restrict__ queries,
                                                float* __restrict__ out) {
    const int n = blockIdx.z;
    const int oBase = blockIdx.x * 128;
    const int uBase = blockIdx.y * 128;

    __shared__ float Qs[2][16 * LB];
    __shared__ float Mss[2][16 * LB];

    const int tx = threadIdx.x, ty = threadIdx.y;
    const int tid = ty * 16 + tx;
    const int ul0 = tid >> 2;
    const int ul1 = ul0 + 64;
    const int dq  = (tid & 3) * 4;

    const float* __restrict__ Mbase = g_Ms + (size_t)n * DD * DD;

    const int ug0 = uBase + ul0, ug1 = uBase + ul1;
    const size_t qoff0 = ((size_t)(ug0 >> 6) * LL + n * WW + (ug0 & 63)) * DD;
    const size_t qoff1 = ((size_t)(ug1 >> 6) * LL + n * WW + (ug1 & 63)) * DD;

    uint64_t acc2[8][4];
#pragma unroll
    for (int a = 0; a < 8; a++)
#pragma unroll
        for (int b = 0; b < 4; b++) acc2[a][b] = 0ull;

    float4 q0, q1, m0, m1;
#define LOADD(D0) do {                                                         \
        q0 = *(const float4*)(queries + qoff0 + (D0) + dq);                    \
        q1 = *(const float4*)(queries + qoff1 + (D0) + dq);                    \
        m0 = *(const float4*)(Mbase + (size_t)(oBase + ul0) * DD + (D0) + dq); \
        m1 = *(const float4*)(Mbase + (size_t)(oBase + ul1) * DD + (D0) + dq); \
    } while (0)

#define STORED(BUF) do {                                                       \
        Qs[BUF][(dq + 0) * LB + ul0] = q0.x; Qs[BUF][(dq + 1) * LB + ul0] = q0.y; \
        Qs[BUF][(dq + 2) * LB + ul0] = q0.z; Qs[BUF][(dq + 3) * LB + ul0] = q0.w; \
        Qs[BUF][(dq + 0) * LB + ul1] = q1.x; Qs[BUF][(dq + 1) * LB + ul1] = q1.y; \
        Qs[BUF][(dq + 2) * LB + ul1] = q1.z; Qs[BUF][(dq + 3) * LB + ul1] = q1.w; \
        Mss[BUF][(dq + 0) * LB + ul0] = m0.x; Mss[BUF][(dq + 1) * LB + ul0] = m0.y; \
        Mss[BUF][(dq + 2) * LB + ul0] = m0.z; Mss[BUF][(dq + 3) * LB + ul0] = m0.w; \
        Mss[BUF][(dq + 0) * LB + ul1] = m1.x; Mss[BUF][(dq + 1) * LB + ul1] = m1.y; \
        Mss[BUF][(dq + 2) * LB + ul1] = m1.z; Mss[BUF][(dq + 3) * LB + ul1] = m1.w; \
    } while (0)

    LOADD(0);
    STORED(0);
    LOADD(16);
    __syncthreads();

    for (int c = 0; c < 16; c++) {
        const int cur = c & 1;
        if (c < 15) STORED(cur ^ 1);
        if (c < 14) LOADD((c + 2) * 16);

#pragma unroll
        for (int kk = 0; kk < 16; kk++) {
            float4 la0 = *(const float4*)&Qs[cur][kk * LB + ty * 8];
            float4 la1 = *(const float4*)&Qs[cur][kk * LB + ty * 8 + 4];
            float4 lb0 = *(const float4*)&Mss[cur][kk * LB + tx * 8];
            float4 lb1 = *(const float4*)&Mss[cur][kk * LB + tx * 8 + 4];
            uint64_t bp[4];
            bp[0] = pkxy(lb0.x, lb0.y); bp[1] = pkxy(lb0.z, lb0.w);
            bp[2] = pkxy(lb1.x, lb1.y); bp[3] = pkxy(lb1.z, lb1.w);
            float laf[8] = {la0.x, la0.y, la0.z, la0.w, la1.x, la1.y, la1.z, la1.w};
#pragma unroll
            for (int a = 0; a < 8; a++) {
                const uint64_t ap = pk2(laf[a]);
                fma2(acc2[a][0], ap, bp[0]);
                fma2(acc2[a][1], ap, bp[1]);
                fma2(acc2[a][2], ap, bp[2]);
                fma2(acc2[a][3], ap, bp[3]);
            }
        }
        __syncthreads();
    }
#undef LOADD
#undef STORED

#pragma unroll
    for (int a = 0; a < 8; a++) {
        const int u = uBase + ty * 8 + a;
        const size_t orow = ((size_t)(u >> 6) * LL + n * WW + (u & 63)) * DD;
        float f[8];
        float2 p;
        p = up2(acc2[a][0]); f[0] = p.x; f[1] = p.y;
        p = up2(acc2[a][1]); f[2] = p.x; f[3] = p.y;
        p = up2(acc2[a][2]); f[4] = p.x; f[5] = p.y;
        p = up2(acc2[a][3]); f[6] = p.x; f[7] = p.y;
        *(float4*)(out + orow + oBase + tx * 8)     = *(float4*)&f[0];
        *(float4*)(out + orow + oBase + tx * 8 + 4) = *(float4*)&f[4];
    }
}

// ---------------------------------------------------------------------------
extern "C" void kernel_launch(void* const* d_in, const int* in_sizes, int n_in,
                              void* d_out, int out_size) {
    const float* keys    = (const float*)d_in[0];
    const float* values  = (const float*)d_in[1];
    const float* queries = (const float*)d_in[2];
    const float* gammas  = (const float*)d_in[3];
    const float* alpha   = (const float*)d_in[4];
    float* out = (float*)d_out;

    (void)in_sizes; (void)n_in; (void)out_size;

    dim3 blk(16, 16);
    k_sums<<<dim3(2, 2, NW * 2), blk>>>(keys, values, gammas, alpha);
    k_scan<<<128, 512>>>();
    k_out<<<dim3(2, 4, NW), blk>>>(queries, out);
}

// round 13
// speedup vs baseline: 5.0363x; 1.1021x over previous
#include <cuda_runtime.h>
#include <math.h>
#include <cstdint>

#define BB 8
#define LL 8192
#define DD 256
#define WW 64
#define NW 128
#define RW 512   /* B*W reduction rows per window */
#define LB 132   /* padded smem row stride (floats) */

// Scratch (allocation-free rule: static __device__ arrays)
__device__ float g_A[(size_t)NW * DD * DD];    // A_n = a*I - Skk_n   (32 MB)
__device__ float g_Svk[(size_t)NW * DD * DD];  // Svk_n               (32 MB)
__device__ float g_Ms[(size_t)NW * DD * DD];   // M snapshots         (32 MB)

// ---- packed fp32x2 helpers (FFMA2) ----------------------------------------
__device__ __forceinline__ uint64_t pk2(float x) {
    uint64_t r; asm("mov.b64 %0, {%1, %1};" : "=l"(r) : "f"(x)); return r;
}
__device__ __forceinline__ void fma2(uint64_t& d, uint64_t a, uint64_t b) {
    asm("fma.rn.f32x2 %0, %1, %2, %3;" : "=l"(d) : "l"(a), "l"(b), "l"(d));
}
__device__ __forceinline__ float2 up2(uint64_t p) {
    float2 r; asm("mov.b64 {%0, %1}, %2;" : "=f"(r.x), "=f"(r.y) : "l"(p)); return r;
}

// ---------------------------------------------------------------------------
// Kernel 1: per-window sums, FFMA2 + dense b-fragment.
//   Skk_n[i,j] = sum_r g_r K_r[i] K_r[j];  Svk_n[i,j] = sum_r g_r V_r[i] K_r[j]
// grid (2, 2, NW*2): z even -> A (= aI - Skk), z odd -> Svk. block (16,16).
// 128x128 tile, 8x8 register tile. Thread's j-columns are tx*4..tx*4+3 and
// 64+tx*4..+3 (lane-dense LDS, b-pairs pre-packed for f32x2). K-chunk 16,
// double-buffered smem, one __syncthreads per chunk.
// ---------------------------------------------------------------------------
__global__ __launch_bounds__(256, 2) void k_sums(const float* __restrict__ keysp,
                                                 const float* __restrict__ values,
                                                 const float* __restrict__ gammas,
                                                 const float* __restrict__ alpha) {
    const int n    = blockIdx.z >> 1;
    const bool isA = (blockIdx.z & 1) == 0;
    const int jBase = blockIdx.x * 128;
    const int iBase = blockIdx.y * 128;
    const float* __restrict__ left = isA ? keysp : values;

    __shared__ float Ls[2][16 * LB];
    __shared__ float Rs[2][16 * LB];

    const int tx = threadIdx.x, ty = threadIdx.y;
    const int tid = ty * 16 + tx;
    const int row0 = tid >> 5;
    const int row1 = row0 + 8;
    const int c4   = (tid & 31) * 4;

    uint64_t acc2[8][4];
#pragma unroll
    for (int a = 0; a < 8; a++)
#pragma unroll
        for (int b = 0; b < 4; b++) acc2[a][b] = 0ull;

    float4 lA0, lA1, rA0, rA1;
    float g0v, g1v;

#define LOADC(R0) do {                                                          \
        const int gr0 = (R0) + row0, gr1 = (R0) + row1;                         \
        const size_t o0 = ((size_t)(gr0 >> 6) * LL + n * WW + (gr0 & 63)) * DD; \
        const size_t o1 = ((size_t)(gr1 >> 6) * LL + n * WW + (gr1 & 63)) * DD; \
        g0v = gammas[(gr0 >> 6) * LL + n * WW + (gr0 & 63)];                    \
        g1v = gammas[(gr1 >> 6) * LL + n * WW + (gr1 & 63)];                    \
        lA0 = *(const float4*)(left  + o0 + iBase + c4);                        \
        lA1 = *(const float4*)(left  + o1 + iBase + c4);                        \
        rA0 = *(const float4*)(keysp + o0 + jBase + c4);                        \
        rA1 = *(const float4*)(keysp + o1 + jBase + c4);                        \
    } while (0)

#define STOREC(BUF) do {                                                        \
        float4 t;                                                               \
        t = lA0; t.x *= g0v; t.y *= g0v; t.z *= g0v; t.w *= g0v;                \
        *(float4*)&Ls[BUF][row0 * LB + c4] = t;                                 \
        t = lA1; t.x *= g1v; t.y *= g1v; t.z *= g1v; t.w *= g1v;                \
        *(float4*)&Ls[BUF][row1 * LB + c4] = t;                                 \
        *(float4*)&Rs[BUF][row0 * LB + c4] = rA0;                               \
        *(float4*)&Rs[BUF][row1 * LB + c4] = rA1;                               \
    } while (0)

    LOADC(0);
    STOREC(0);
    LOADC(16);
    __syncthreads();

    for (int c = 0; c < 32; c++) {
        const int cur = c & 1;
        if (c < 31) STOREC(cur ^ 1);
        if (c < 30) LOADC((c + 2) * 16);

#pragma unroll
        for (int kk = 0; kk < 16; kk++) {
            // a-fragment: rows ty*8 .. ty*8+7 (broadcast within warp)
            float4 la0 = *(const float4*)&Ls[cur][kk * LB + ty * 8];
            float4 la1 = *(const float4*)&Ls[cur][kk * LB + ty * 8 + 4];
            // b-fragment: cols tx*4 and 64+tx*4, loaded as packed f32x2 pairs
            ulonglong2 lbp0 = *(const ulonglong2*)&Rs[cur][kk * LB + tx * 4];
            ulonglong2 lbp1 = *(const ulonglong2*)&Rs[cur][kk * LB + 64 + tx * 4];
            float laf[8] = {la0.x, la0.y, la0.z, la0.w, la1.x, la1.y, la1.z, la1.w};
#pragma unroll
            for (int a = 0; a < 8; a++) {
                const uint64_t ap = pk2(laf[a]);
                fma2(acc2[a][0], ap, lbp0.x);
                fma2(acc2[a][1], ap, lbp0.y);
                fma2(acc2[a][2], ap, lbp1.x);
                fma2(acc2[a][3], ap, lbp1.y);
            }
        }
        __syncthreads();
    }
#undef LOADC
#undef STOREC

    const float aSig = 1.f / (1.f + expf(-alpha[0]));
    float* dst = isA ? g_A : g_Svk;
    const size_t base = (size_t)n * DD * DD;
#pragma unroll
    for (int a = 0; a < 8; a++) {
        const int i = iBase + ty * 8 + a;
        float f[8];
        float2 p;
        p = up2(acc2[a][0]); f[0] = p.x; f[1] = p.y;
        p = up2(acc2[a][1]); f[2] = p.x; f[3] = p.y;
        p = up2(acc2[a][2]); f[4] = p.x; f[5] = p.y;
        p = up2(acc2[a][3]); f[6] = p.x; f[7] = p.y;
        if (isA) {
#pragma unroll
            for (int b = 0; b < 4; b++) {
                const int j0 = jBase + tx * 4 + b;
                const int j1 = jBase + 64 + tx * 4 + b;
                f[b]     = ((i == j0) ? aSig : 0.f) - f[b];
                f[b + 4] = ((i == j1) ? aSig : 0.f) - f[b + 4];
            }
        }
        *(float4*)(dst + base + (size_t)i * DD + jBase + tx * 4)      = *(float4*)&f[0];
        *(float4*)(dst + base + (size_t)i * DD + jBase + 64 + tx * 4) = *(float4*)&f[4];
    }
}

// ---------------------------------------------------------------------------
// Kernel 2: sequential scan, cluster-pair column split + mbarrier exchange
// (unchanged — round 8 winner).
// ---------------------------------------------------------------------------
__global__ __launch_bounds__(512) __cluster_dims__(2, 1, 1) void k_scan() {
    __shared__ float4 Msm4[2][DD];
    __shared__ float part[16][4][128];
    __shared__ uint64_t mbar[2];

    const int t = threadIdx.x;
    const int jg = t & 31;
    const int hq = t >> 5;
    const int dBase = hq * 16;

    uint32_t rank;
    asm("mov.u32 %0, %%cluster_ctarank;" : "=r"(rank));
    const uint32_t prank = rank ^ 1u;
    const int ch = (int)rank;
    const int r0 = (blockIdx.x >> 1) * 4;
    const int j4 = ch * 128 + jg * 4;

    const int rr  = t >> 7;
    const int jl  = t & 127;
    const int jgl = ch * 128 + jl;

    if (t < DD) Msm4[0][t] = make_float4(0.f, 0.f, 0.f, 0.f);
    if (t < 2) {
        uint32_t mb;
        {
            uint64_t tmp;
            asm("cvta.to.shared.u64 %0, %1;" : "=l"(tmp) : "l"((const void*)&mbar[t]));
            mb = (uint32_t)tmp;
        }
        asm volatile("mbarrier.init.shared.b64 [%0], %1;" :: "r"(mb), "r"(512u) : "memory");
    }
    __syncthreads();
    asm volatile("barrier.cluster.arrive.aligned;" ::: "memory");
    asm volatile("barrier.cluster.wait.aligned;" ::: "memory");

    uint32_t msmBase, mbarBase;
    {
        uint64_t tmp;
        asm("cvta.to.shared.u64 %0, %1;" : "=l"(tmp) : "l"((const void*)&Msm4[0][0]));
        msmBase = (uint32_t)tmp;
        asm("cvta.to.shared.u64 %0, %1;" : "=l"(tmp) : "l"((const void*)&mbar[0]));
        mbarBase = (uint32_t)tmp;
    }

    float4 avA[8], avB[8];
#pragma unroll
    for (int d = 0; d < 8; d++) {
        avA[d] = *(const float4*)(g_A + (size_t)(dBase + d) * DD + j4);
        avB[d] = *(const float4*)(g_A + (size_t)(dBase + 8 + d) * DD + j4);
    }

    for (int n = 0; n < NW; n++) {
        const int cur = n & 1;
        const int nb  = cur ^ 1;
        const uint32_t par = (uint32_t)((n >> 1) & 1);

        const float sval = g_Svk[(size_t)n * DD * DD + (size_t)(r0 + rr) * DD + jgl];

        float4 a0 = {0,0,0,0}, a1 = {0,0,0,0}, a2 = {0,0,0,0}, a3 = {0,0,0,0};
#pragma unroll
        for (int d = 0; d < 8; d++) {
            const float4 m = Msm4[cur][dBase + d];
            const float4 a = avA[d];
            a0.x = fmaf(m.x, a.x, a0.x); a0.y = fmaf(m.x, a.y, a0.y);
            a0.z = fmaf(m.x, a.z, a0.z); a0.w = fmaf(m.x, a.w, a0.w);
            a1.x = fmaf(m.y, a.x, a1.x); a1.y = fmaf(m.y, a.y, a1.y);
            a1.z = fmaf(m.y, a.z, a1.z); a1.w = fmaf(m.y, a.w, a1.w);
            a2.x = fmaf(m.z, a.x, a2.x); a2.y = fmaf(m.z, a.y, a2.y);
            a2.z = fmaf(m.z, a.z, a2.z); a2.w = fmaf(m.z, a.w, a2.w);
            a3.x = fmaf(m.w, a.x, a3.x); a3.y = fmaf(m.w, a.y, a3.y);
            a3.z = fmaf(m.w, a.z, a3.z); a3.w = fmaf(m.w, a.w, a3.w);
        }
#pragma unroll
        for (int d = 0; d < 8; d++) {
            const float4 m = Msm4[cur][dBase + 8 + d];
            const float4 a = avB[d];
            a0.x = fmaf(m.x, a.x, a0.x); a0.y = fmaf(m.x, a.y, a0.y);
            a0.z = fmaf(m.x, a.z, a0.z); a0.w = fmaf(m.x, a.w, a0.w);
            a1.x = fmaf(m.y, a.x, a1.x); a1.y = fmaf(m.y, a.y, a1.y);
            a1.z = fmaf(m.y, a.z, a1.z); a1.w = fmaf(m.y, a.w, a1.w);
            a2.x = fmaf(m.z, a.x, a2.x); a2.y = fmaf(m.z, a.y, a2.y);
            a2.z = fmaf(m.z, a.z, a2.z); a2.w = fmaf(m.z, a.w, a2.w);
            a3.x = fmaf(m.w, a.x, a3.x); a3.y = fmaf(m.w, a.y, a3.y);
            a3.z = fmaf(m.w, a.z, a3.z); a3.w = fmaf(m.w, a.w, a3.w);
        }

        *(float4*)&part[hq][0][jg * 4] = a0;
        *(float4*)&part[hq][1][jg * 4] = a1;
        *(float4*)&part[hq][2][jg * 4] = a2;
        *(float4*)&part[hq][3][jg * 4] = a3;

        if (n < NW - 1) {
            const float* __restrict__ An = g_A + (size_t)(n + 1) * DD * DD;
#pragma unroll
            for (int d = 0; d < 8; d++) {
                avA[d] = *(const float4*)(An + (size_t)(dBase + d) * DD + j4);
                avB[d] = *(const float4*)(An + (size_t)(dBase + 8 + d) * DD + j4);
            }
        }
        __syncthreads();

        float u = 0.f;
#pragma unroll
        for (int q = 0; q < 16; q++) u += part[q][rr][jl];
        u += sval;

        const uint32_t off = (uint32_t)(nb * DD * 16 + (jgl * 4 + rr) * 4);
        const uint32_t laddr = msmBase + off;
        asm volatile("st.shared.f32 [%0], %1;" :: "r"(laddr), "f"(u));
        {
            uint32_t raddr;
            asm("mapa.shared::cluster.u32 %0, %1, %2;" : "=r"(raddr) : "r"(laddr), "r"(prank));
            asm volatile("st.shared::cluster.f32 [%0], %1;" :: "r"(raddr), "f"(u));
            uint32_t rmbar;
            asm("mapa.shared::cluster.u32 %0, %1, %2;"
                : "=r"(rmbar) : "r"(mbarBase + (uint32_t)(nb * 8)), "r"(prank));
            asm volatile("mbarrier.arrive.release.cluster.shared::cluster.b64 _, [%0];"
                         :: "r"(rmbar) : "memory");
        }

        g_Ms[(size_t)n * DD * DD + (size_t)(r0 + rr) * DD + jgl] = u;

        __syncthreads();

        asm volatile(
            "{\n\t"
            ".reg .pred P;\n\t"
            "KSW_%=:\n\t"
            "mbarrier.try_wait.parity.acquire.cluster.shared::cta.b64 P, [%0], %1, 0x989680;\n\t"
            "@!P bra KSW_%=;\n\t"
            "}"
            :: "r"(mbarBase + (uint32_t)(nb * 8)), "r"(par) : "memory");
    }

    asm volatile("barrier.cluster.arrive.aligned;" ::: "memory");
    asm volatile("barrier.cluster.wait.aligned;" ::: "memory");
}

// ---------------------------------------------------------------------------
// Kernel 3: retrieval, FFMA2 + dense b-fragment.
//   out[b, n*W+w, o] = sum_d Q[b, n*W+w, d] * Ms_n[o, d]
// grid (2, 4, NW). 128x128 tile, 8x8 register tile (cols tx*4 & 64+tx*4),
// double-buffered smem with one sync per 16-d chunk.
// ---------------------------------------------------------------------------
__global__ __launch_bounds__(256, 2) void k_out(const float* __restrict__ queries,
                                                float* __restrict__ out) {
    const int n = blockIdx.z;
    const int oBase = blockIdx.x * 128;
    const int uBase = blockIdx.y * 128;

    __shared__ float Qs[2][16 * LB];
    __shared__ float Mss[2][16 * LB];

    const int tx = threadIdx.x, ty = threadIdx.y;
    const int tid = ty * 16 + tx;
    const int ul0 = tid >> 2;
    const int ul1 = ul0 + 64;
    const int dq  = (tid & 3) * 4;

    const float* __restrict__ Mbase = g_Ms + (size_t)n * DD * DD;

    const int ug0 = uBase + ul0, ug1 = uBase + ul1;
    const size_t qoff0 = ((size_t)(ug0 >> 6) * LL + n * WW + (ug0 & 63)) * DD;
    const size_t qoff1 = ((size_t)(ug1 >> 6) * LL + n * WW + (ug1 & 63)) * DD;

    uint64_t acc2[8][4];
#pragma unroll
    for (int a = 0; a < 8; a++)
#pragma unroll
        for (int b = 0; b < 4; b++) acc2[a][b] = 0ull;

    float4 q0, q1, m0, m1;
#define LOADD(D0) do {                                                         \
        q0 = *(const float4*)(queries + qoff0 + (D0) + dq);                    \
        q1 = *(const float4*)(queries + qoff1 + (D0) + dq);                    \
        m0 = *(const float4*)(Mbase + (size_t)(oBase + ul0) * DD + (D0) + dq); \
        m1 = *(const float4*)(Mbase + (size_t)(oBase + ul1) * DD + (D0) + dq); \
    } while (0)

#define STORED(BUF) do {                                                       \
        Qs[BUF][(dq + 0) * LB + ul0] = q0.x; Qs[BUF][(dq + 1) * LB + ul0] = q0.y; \
        Qs[BUF][(dq + 2) * LB + ul0] = q0.z; Qs[BUF][(dq + 3) * LB + ul0] = q0.w; \
        Qs[BUF][(dq + 0) * LB + ul1] = q1.x; Qs[BUF][(dq + 1) * LB + ul1] = q1.y; \
        Qs[BUF][(dq + 2) * LB + ul1] = q1.z; Qs[BUF][(dq + 3) * LB + ul1] = q1.w; \
        Mss[BUF][(dq + 0) * LB + ul0] = m0.x; Mss[BUF][(dq + 1) * LB + ul0] = m0.y; \
        Mss[BUF][(dq + 2) * LB + ul0] = m0.z; Mss[BUF][(dq + 3) * LB + ul0] = m0.w; \
        Mss[BUF][(dq + 0) * LB + ul1] = m1.x; Mss[BUF][(dq + 1) * LB + ul1] = m1.y; \
        Mss[BUF][(dq + 2) * LB + ul1] = m1.z; Mss[BUF][(dq + 3) * LB + ul1] = m1.w; \
    } while (0)

    LOADD(0);
    STORED(0);
    LOADD(16);
    __syncthreads();

    for (int c = 0; c < 16; c++) {
        const int cur = c & 1;
        if (c < 15) STORED(cur ^ 1);
        if (c < 14) LOADD((c + 2) * 16);

#pragma unroll
        for (int kk = 0; kk < 16; kk++) {
            float4 la0 = *(const float4*)&Qs[cur][kk * LB + ty * 8];
            float4 la1 = *(const float4*)&Qs[cur][kk * LB + ty * 8 + 4];
            ulonglong2 lbp0 = *(const ulonglong2*)&Mss[cur][kk * LB + tx * 4];
            ulonglong2 lbp1 = *(const ulonglong2*)&Mss[cur][kk * LB + 64 + tx * 4];
            float laf[8] = {la0.x, la0.y, la0.z, la0.w, la1.x, la1.y, la1.z, la1.w};
#pragma unroll
            for (int a = 0; a < 8; a++) {
                const uint64_t ap = pk2(laf[a]);
                fma2(acc2[a][0], ap, lbp0.x);
                fma2(acc2[a][1], ap, lbp0.y);
                fma2(acc2[a][2], ap, lbp1.x);
                fma2(acc2[a][3], ap, lbp1.y);
            }
        }
        __syncthreads();
    }
#undef LOADD
#undef STORED

#pragma unroll
    for (int a = 0; a < 8; a++) {
        const int u = uBase + ty * 8 + a;
        const size_t orow = ((size_t)(u >> 6) * LL + n * WW + (u & 63)) * DD;
        float f[8];
        float2 p;
        p = up2(acc2[a][0]); f[0] = p.x; f[1] = p.y;
        p = up2(acc2[a][1]); f[2] = p.x; f[3] = p.y;
        p = up2(acc2[a][2]); f[4] = p.x; f[5] = p.y;
        p = up2(acc2[a][3]); f[6] = p.x; f[7] = p.y;
        *(float4*)(out + orow + oBase + tx * 4)      = *(float4*)&f[0];
        *(float4*)(out + orow + oBase + 64 + tx * 4) = *(float4*)&f[4];
    }
}

// ---------------------------------------------------------------------------
extern "C" void kernel_launch(void* const* d_in, const int* in_sizes, int n_in,
                              void* d_out, int out_size) {
    const float* keys    = (const float*)d_in[0];
    const float* values  = (const float*)d_in[1];
    const float* queries = (const float*)d_in[2];
    const float* gammas  = (const float*)d_in[3];
    const float* alpha   = (const float*)d_in[4];
    float* out = (float*)d_out;

    (void)in_sizes; (void)n_in; (void)out_size;

    dim3 blk(16, 16);
    k_sums<<<dim3(2, 2, NW * 2), blk>>>(keys, values, gammas, alpha);
    k_scan<<<128, 512>>>();
    k_out<<<dim3(2, 4, NW), blk>>>(queries, out);
}